// round 5
// baseline (speedup 1.0000x reference)
#include <cuda_runtime.h>
#include <cuda_bf16.h>

#define N_NODES 100000
#define N_EDGES 1600000
#define IN_CH 128
#define HID_CH 64
#define OUT_CH 64

// ---------------- scratch (device globals; no allocation allowed) ------------
// NOTE: these must ONLY be referenced from device code. Passing them as kernel
// arguments from host code passes the HOST shadow address (silently readable/
// writable on GB300 via ATS) — that was the R1-R3 bug.
__device__ int   g_idx64;                   // 1 if edge_index is int64, 0 if int32
__device__ int   g_row[N_EDGES];
__device__ int   g_col[N_EDGES];
__device__ int   g_deg[N_NODES];
__device__ float g_dinv[N_NODES];
__device__ float g_hs [N_NODES * HID_CH];   // dinv-scaled features (msg source)
__device__ float g_acc[N_NODES * HID_CH];   // layer-1 scatter accumulator

// ---------------- edge-index dtype probe + convert ---------------------------
__global__ void probe_kernel(const void* ei) {
    __shared__ int ok;
    if (threadIdx.x == 0) ok = 1;
    __syncthreads();
    const long long* p = (const long long*)ei;
    for (int i = threadIdx.x; i < 1024; i += blockDim.x) {
        long long v = p[i];
        if (v < 0 || v >= N_NODES) ok = 0;   // benign race, only writes 0
    }
    __syncthreads();
    if (threadIdx.x == 0) g_idx64 = ok;
}

__global__ void convert_kernel(const void* ei) {
    int e = blockIdx.x * blockDim.x + threadIdx.x;
    if (e >= N_EDGES) return;
    long long r, c;
    if (g_idx64) {
        const long long* p = (const long long*)ei;
        r = p[e]; c = p[e + N_EDGES];
    } else {
        const int* p = (const int*)ei;
        r = p[e]; c = p[e + N_EDGES];
    }
    if (r < 0) r = 0; if (r >= N_NODES) r = N_NODES - 1;
    if (c < 0) c = 0; if (c >= N_NODES) c = N_NODES - 1;
    g_row[e] = (int)r;
    g_col[e] = (int)c;
}

// ---------------- degree ----------------------------------------------------
__global__ void init_deg_kernel() {
    int i = blockIdx.x * blockDim.x + threadIdx.x;
    if (i < N_NODES) g_deg[i] = 1;   // self-loop
}

__global__ void count_deg_kernel() {
    int e = blockIdx.x * blockDim.x + threadIdx.x;
    if (e < N_EDGES) atomicAdd(&g_deg[g_col[e]], 1);
}

__global__ void dinv_kernel() {
    int i = blockIdx.x * blockDim.x + threadIdx.x;
    if (i < N_NODES) g_dinv[i] = rsqrtf((float)g_deg[i]);
}

// ---------------- layer-1 GEMM: hs = dinv * (x @ W1); acc = hs --------------
__global__ void __launch_bounds__(256) gemm1_kernel(
    const float* __restrict__ x, const float* __restrict__ W1)
{
    __shared__ float Ws[IN_CH * HID_CH];     // 32 KB
    __shared__ float xs[16][IN_CH];          // 8 KB
    int tid = threadIdx.x;

    {
        const float4* w4 = (const float4*)W1;
        float4* ws4 = (float4*)Ws;
        #pragma unroll
        for (int i = tid; i < (IN_CH * HID_CH) / 4; i += 256) ws4[i] = w4[i];
    }
    int row0 = blockIdx.x * 16;
    {
        const float4* x4 = (const float4*)(x + (size_t)row0 * IN_CH);
        float4* xs4 = (float4*)&xs[0][0];
        #pragma unroll
        for (int i = tid; i < (16 * IN_CH) / 4; i += 256) xs4[i] = x4[i];
    }
    __syncthreads();

    int c  = tid & 63;
    int rg = tid >> 6;                       // 0..3 -> rows rg*4..rg*4+3
    const float* x0 = xs[rg * 4 + 0];
    const float* x1 = xs[rg * 4 + 1];
    const float* x2 = xs[rg * 4 + 2];
    const float* x3 = xs[rg * 4 + 3];

    float a0 = 0.f, a1 = 0.f, a2 = 0.f, a3 = 0.f;
    #pragma unroll 8
    for (int k = 0; k < IN_CH; k++) {
        float wv = Ws[k * HID_CH + c];
        a0 = fmaf(x0[k], wv, a0);
        a1 = fmaf(x1[k], wv, a1);
        a2 = fmaf(x2[k], wv, a2);
        a3 = fmaf(x3[k], wv, a3);
    }
    int r = row0 + rg * 4;
    float d0 = g_dinv[r], d1 = g_dinv[r + 1], d2 = g_dinv[r + 2], d3 = g_dinv[r + 3];
    float v;
    v = a0 * d0; g_hs[(size_t)(r + 0) * HID_CH + c] = v; g_acc[(size_t)(r + 0) * HID_CH + c] = v;
    v = a1 * d1; g_hs[(size_t)(r + 1) * HID_CH + c] = v; g_acc[(size_t)(r + 1) * HID_CH + c] = v;
    v = a2 * d2; g_hs[(size_t)(r + 2) * HID_CH + c] = v; g_acc[(size_t)(r + 2) * HID_CH + c] = v;
    v = a3 * d3; g_hs[(size_t)(r + 3) * HID_CH + c] = v; g_acc[(size_t)(r + 3) * HID_CH + c] = v;
}

// ---------------- edge aggregation: dst[col] += g_hs[row] (64 ch) -----------
// 16 threads per edge; each handles one float4 (4 channels). Vector RED.
// Device globals referenced DIRECTLY (not via host-passed params).
__global__ void __launch_bounds__(256) agg1_kernel()
{
    int t = blockIdx.x * blockDim.x + threadIdx.x;
    int e = t >> 4;
    int q = t & 15;
    if (e >= N_EDGES) return;
    int r = g_row[e];
    int c = g_col[e];
    const float4* s4 = (const float4*)g_hs;
    float4 v = s4[(size_t)r * 16 + q];
    float* d = g_acc + ((size_t)c * HID_CH + (q * 4));
    asm volatile("red.global.add.v4.f32 [%0], {%1, %2, %3, %4};"
                 :: "l"(d), "f"(v.x), "f"(v.y), "f"(v.z), "f"(v.w)
                 : "memory");
}

__global__ void __launch_bounds__(256) agg2_kernel(float* __restrict__ dst)
{
    int t = blockIdx.x * blockDim.x + threadIdx.x;
    int e = t >> 4;
    int q = t & 15;
    if (e >= N_EDGES) return;
    int r = g_row[e];
    int c = g_col[e];
    const float4* s4 = (const float4*)g_hs;
    float4 v = s4[(size_t)r * 16 + q];
    float* d = dst + ((size_t)c * HID_CH + (q * 4));
    asm volatile("red.global.add.v4.f32 [%0], {%1, %2, %3, %4};"
                 :: "l"(d), "f"(v.x), "f"(v.y), "f"(v.z), "f"(v.w)
                 : "memory");
}

// ---------------- layer-2: h1 = relu(dinv*acc + b1); gs = dinv*(h1@W2) ------
// writes gs into g_hs (reuse) and initializes d_out = gs (self-loop term)
__global__ void __launch_bounds__(256) layer2_kernel(
    const float* __restrict__ b1, const float* __restrict__ W2,
    float* __restrict__ outp)
{
    __shared__ float Ws[HID_CH * OUT_CH];    // 16 KB
    __shared__ float hs[16][HID_CH];         // 4 KB
    int tid = threadIdx.x;

    {
        const float4* w4 = (const float4*)W2;
        float4* ws4 = (float4*)Ws;
        #pragma unroll
        for (int i = tid; i < (HID_CH * OUT_CH) / 4; i += 256) ws4[i] = w4[i];
    }
    int row0 = blockIdx.x * 16;
    #pragma unroll
    for (int i = tid; i < 16 * HID_CH; i += 256) {
        int rr = i >> 6;
        int cc = i & 63;
        int r  = row0 + rr;
        float v = fmaf(g_dinv[r], g_acc[(size_t)r * HID_CH + cc], __ldg(&b1[cc]));
        hs[rr][cc] = fmaxf(v, 0.f);
    }
    __syncthreads();

    int c  = tid & 63;
    int rg = tid >> 6;
    const float* x0 = hs[rg * 4 + 0];
    const float* x1 = hs[rg * 4 + 1];
    const float* x2 = hs[rg * 4 + 2];
    const float* x3 = hs[rg * 4 + 3];

    float a0 = 0.f, a1 = 0.f, a2 = 0.f, a3 = 0.f;
    #pragma unroll 8
    for (int k = 0; k < HID_CH; k++) {
        float wv = Ws[k * OUT_CH + c];
        a0 = fmaf(x0[k], wv, a0);
        a1 = fmaf(x1[k], wv, a1);
        a2 = fmaf(x2[k], wv, a2);
        a3 = fmaf(x3[k], wv, a3);
    }
    int r = row0 + rg * 4;
    float d0 = g_dinv[r], d1 = g_dinv[r + 1], d2 = g_dinv[r + 2], d3 = g_dinv[r + 3];
    float v;
    v = a0 * d0; g_hs[(size_t)(r + 0) * OUT_CH + c] = v; outp[(size_t)(r + 0) * OUT_CH + c] = v;
    v = a1 * d1; g_hs[(size_t)(r + 1) * OUT_CH + c] = v; outp[(size_t)(r + 1) * OUT_CH + c] = v;
    v = a2 * d2; g_hs[(size_t)(r + 2) * OUT_CH + c] = v; outp[(size_t)(r + 2) * OUT_CH + c] = v;
    v = a3 * d3; g_hs[(size_t)(r + 3) * OUT_CH + c] = v; outp[(size_t)(r + 3) * OUT_CH + c] = v;
}

// ---------------- final: out = dinv * out + b2 -------------------------------
__global__ void final_kernel(float* __restrict__ outp, const float* __restrict__ b2) {
    int i = blockIdx.x * blockDim.x + threadIdx.x;
    if (i < N_NODES * OUT_CH) {
        int r = i >> 6;
        int c = i & 63;
        outp[i] = fmaf(g_dinv[r], outp[i], b2[c]);
    }
}

extern "C" void kernel_launch(void* const* d_in, const int* in_sizes, int n_in,
                              void* d_out, int out_size)
{
    // ---- identify inputs by element count (robust to any metadata order) ----
    const float* x  = nullptr;
    const void*  ei = nullptr;
    const float* W1 = nullptr;
    const float* b1 = nullptr;
    const float* W2 = nullptr;
    const float* b2 = nullptr;
    for (int i = 0; i < n_in; i++) {
        long long s = in_sizes[i];
        if      (s == (long long)N_NODES * IN_CH) x  = (const float*)d_in[i];
        else if (s == 2LL * N_EDGES)              ei = d_in[i];
        else if (s == (long long)IN_CH * HID_CH)  W1 = (const float*)d_in[i];
        else if (s == (long long)HID_CH * OUT_CH) W2 = (const float*)d_in[i];
        else if (s == HID_CH) { if (!b1) b1 = (const float*)d_in[i];
                                else     b2 = (const float*)d_in[i]; }
    }
    if (!x || !ei || !W1 || !b1 || !W2 || !b2) {
        x  = (const float*)d_in[0];
        ei = d_in[1];
        W1 = (const float*)d_in[2];
        b1 = (const float*)d_in[3];
        W2 = (const float*)d_in[4];
        b2 = (const float*)d_in[5];
    }
    float* outp = (float*)d_out;

    // edge-index dtype probe + conversion to int
    probe_kernel<<<1, 256>>>(ei);
    convert_kernel<<<(N_EDGES + 255) / 256, 256>>>(ei);

    // degree + dinv
    init_deg_kernel<<<(N_NODES + 255) / 256, 256>>>();
    count_deg_kernel<<<(N_EDGES + 255) / 256, 256>>>();
    dinv_kernel<<<(N_NODES + 255) / 256, 256>>>();

    const int AGG_BLOCKS = (N_EDGES * 16) / 256;   // 100000 exactly

    // layer 1
    gemm1_kernel<<<N_NODES / 16, 256>>>(x, W1);
    agg1_kernel<<<AGG_BLOCKS, 256>>>();

    // layer 2 (epilogue1 + gemm2 fused); initializes d_out with self-loop term
    layer2_kernel<<<N_NODES / 16, 256>>>(b1, W2, outp);
    agg2_kernel<<<AGG_BLOCKS, 256>>>(outp);

    // epilogue 2
    final_kernel<<<(N_NODES * OUT_CH + 255) / 256, 256>>>(outp, b2);
}

// round 6
// speedup vs baseline: 1.0042x; 1.0042x over previous
#include <cuda_runtime.h>
#include <cuda_bf16.h>

#define N_NODES 100000
#define N_EDGES 1600000
#define IN_CH 128
#define HID_CH 64
#define OUT_CH 64

// ---------------- scratch (device globals; no allocation allowed) ------------
// NOTE: these must ONLY be referenced from device code. Passing them as kernel
// arguments from host code passes the HOST shadow address (silently readable/
// writable on GB300 via ATS) — that was the R1-R3 bug.
__device__ int   g_idx64;                   // 1 if edge_index is int64, 0 if int32
__device__ int   g_row[N_EDGES];
__device__ int   g_col[N_EDGES];
__device__ int   g_deg[N_NODES];
__device__ float g_dinv[N_NODES];
__device__ float g_hs [N_NODES * HID_CH];   // dinv-scaled features (msg source)
__device__ float g_acc[N_NODES * HID_CH];   // layer-1 scatter accumulator

// ---------------- edge-index dtype probe + convert ---------------------------
__global__ void probe_kernel(const void* ei) {
    __shared__ int ok;
    if (threadIdx.x == 0) ok = 1;
    __syncthreads();
    const long long* p = (const long long*)ei;
    for (int i = threadIdx.x; i < 1024; i += blockDim.x) {
        long long v = p[i];
        if (v < 0 || v >= N_NODES) ok = 0;   // benign race, only writes 0
    }
    __syncthreads();
    if (threadIdx.x == 0) g_idx64 = ok;
}

__global__ void convert_kernel(const void* ei) {
    int e = blockIdx.x * blockDim.x + threadIdx.x;
    if (e >= N_EDGES) return;
    long long r, c;
    if (g_idx64) {
        const long long* p = (const long long*)ei;
        r = p[e]; c = p[e + N_EDGES];
    } else {
        const int* p = (const int*)ei;
        r = p[e]; c = p[e + N_EDGES];
    }
    if (r < 0) r = 0; if (r >= N_NODES) r = N_NODES - 1;
    if (c < 0) c = 0; if (c >= N_NODES) c = N_NODES - 1;
    g_row[e] = (int)r;
    g_col[e] = (int)c;
}

// ---------------- degree ----------------------------------------------------
__global__ void init_deg_kernel() {
    int i = blockIdx.x * blockDim.x + threadIdx.x;
    if (i < N_NODES) g_deg[i] = 1;   // self-loop
}

__global__ void count_deg_kernel() {
    int e = blockIdx.x * blockDim.x + threadIdx.x;
    if (e < N_EDGES) atomicAdd(&g_deg[g_col[e]], 1);
}

__global__ void dinv_kernel() {
    int i = blockIdx.x * blockDim.x + threadIdx.x;
    if (i < N_NODES) g_dinv[i] = rsqrtf((float)g_deg[i]);
}

// ---------------- layer-1 GEMM: hs = dinv * (x @ W1); acc = hs --------------
__global__ void __launch_bounds__(256) gemm1_kernel(
    const float* __restrict__ x, const float* __restrict__ W1)
{
    __shared__ float Ws[IN_CH * HID_CH];     // 32 KB
    __shared__ float xs[16][IN_CH];          // 8 KB
    int tid = threadIdx.x;

    {
        const float4* w4 = (const float4*)W1;
        float4* ws4 = (float4*)Ws;
        #pragma unroll
        for (int i = tid; i < (IN_CH * HID_CH) / 4; i += 256) ws4[i] = w4[i];
    }
    int row0 = blockIdx.x * 16;
    {
        const float4* x4 = (const float4*)(x + (size_t)row0 * IN_CH);
        float4* xs4 = (float4*)&xs[0][0];
        #pragma unroll
        for (int i = tid; i < (16 * IN_CH) / 4; i += 256) xs4[i] = x4[i];
    }
    __syncthreads();

    int c  = tid & 63;
    int rg = tid >> 6;                       // 0..3 -> rows rg*4..rg*4+3
    const float* x0 = xs[rg * 4 + 0];
    const float* x1 = xs[rg * 4 + 1];
    const float* x2 = xs[rg * 4 + 2];
    const float* x3 = xs[rg * 4 + 3];

    float a0 = 0.f, a1 = 0.f, a2 = 0.f, a3 = 0.f;
    #pragma unroll 8
    for (int k = 0; k < IN_CH; k++) {
        float wv = Ws[k * HID_CH + c];
        a0 = fmaf(x0[k], wv, a0);
        a1 = fmaf(x1[k], wv, a1);
        a2 = fmaf(x2[k], wv, a2);
        a3 = fmaf(x3[k], wv, a3);
    }
    int r = row0 + rg * 4;
    float d0 = g_dinv[r], d1 = g_dinv[r + 1], d2 = g_dinv[r + 2], d3 = g_dinv[r + 3];
    float v;
    v = a0 * d0; g_hs[(size_t)(r + 0) * HID_CH + c] = v; g_acc[(size_t)(r + 0) * HID_CH + c] = v;
    v = a1 * d1; g_hs[(size_t)(r + 1) * HID_CH + c] = v; g_acc[(size_t)(r + 1) * HID_CH + c] = v;
    v = a2 * d2; g_hs[(size_t)(r + 2) * HID_CH + c] = v; g_acc[(size_t)(r + 2) * HID_CH + c] = v;
    v = a3 * d3; g_hs[(size_t)(r + 3) * HID_CH + c] = v; g_acc[(size_t)(r + 3) * HID_CH + c] = v;
}

// ---------------- edge aggregation: dst[col] += g_hs[row] (64 ch) -----------
// 16 threads per edge; each handles one float4 (4 channels). Vector RED.
// Device globals referenced DIRECTLY (not via host-passed params).
__global__ void __launch_bounds__(256) agg1_kernel()
{
    int t = blockIdx.x * blockDim.x + threadIdx.x;
    int e = t >> 4;
    int q = t & 15;
    if (e >= N_EDGES) return;
    int r = g_row[e];
    int c = g_col[e];
    const float4* s4 = (const float4*)g_hs;
    float4 v = s4[(size_t)r * 16 + q];
    float* d = g_acc + ((size_t)c * HID_CH + (q * 4));
    asm volatile("red.global.add.v4.f32 [%0], {%1, %2, %3, %4};"
                 :: "l"(d), "f"(v.x), "f"(v.y), "f"(v.z), "f"(v.w)
                 : "memory");
}

__global__ void __launch_bounds__(256) agg2_kernel(float* __restrict__ dst)
{
    int t = blockIdx.x * blockDim.x + threadIdx.x;
    int e = t >> 4;
    int q = t & 15;
    if (e >= N_EDGES) return;
    int r = g_row[e];
    int c = g_col[e];
    const float4* s4 = (const float4*)g_hs;
    float4 v = s4[(size_t)r * 16 + q];
    float* d = dst + ((size_t)c * HID_CH + (q * 4));
    asm volatile("red.global.add.v4.f32 [%0], {%1, %2, %3, %4};"
                 :: "l"(d), "f"(v.x), "f"(v.y), "f"(v.z), "f"(v.w)
                 : "memory");
}

// ---------------- layer-2: h1 = relu(dinv*acc + b1); gs = dinv*(h1@W2) ------
// writes gs into g_hs (reuse) and initializes d_out = gs (self-loop term)
__global__ void __launch_bounds__(256) layer2_kernel(
    const float* __restrict__ b1, const float* __restrict__ W2,
    float* __restrict__ outp)
{
    __shared__ float Ws[HID_CH * OUT_CH];    // 16 KB
    __shared__ float hs[16][HID_CH];         // 4 KB
    int tid = threadIdx.x;

    {
        const float4* w4 = (const float4*)W2;
        float4* ws4 = (float4*)Ws;
        #pragma unroll
        for (int i = tid; i < (HID_CH * OUT_CH) / 4; i += 256) ws4[i] = w4[i];
    }
    int row0 = blockIdx.x * 16;
    #pragma unroll
    for (int i = tid; i < 16 * HID_CH; i += 256) {
        int rr = i >> 6;
        int cc = i & 63;
        int r  = row0 + rr;
        float v = fmaf(g_dinv[r], g_acc[(size_t)r * HID_CH + cc], __ldg(&b1[cc]));
        hs[rr][cc] = fmaxf(v, 0.f);
    }
    __syncthreads();

    int c  = tid & 63;
    int rg = tid >> 6;
    const float* x0 = hs[rg * 4 + 0];
    const float* x1 = hs[rg * 4 + 1];
    const float* x2 = hs[rg * 4 + 2];
    const float* x3 = hs[rg * 4 + 3];

    float a0 = 0.f, a1 = 0.f, a2 = 0.f, a3 = 0.f;
    #pragma unroll 8
    for (int k = 0; k < HID_CH; k++) {
        float wv = Ws[k * OUT_CH + c];
        a0 = fmaf(x0[k], wv, a0);
        a1 = fmaf(x1[k], wv, a1);
        a2 = fmaf(x2[k], wv, a2);
        a3 = fmaf(x3[k], wv, a3);
    }
    int r = row0 + rg * 4;
    float d0 = g_dinv[r], d1 = g_dinv[r + 1], d2 = g_dinv[r + 2], d3 = g_dinv[r + 3];
    float v;
    v = a0 * d0; g_hs[(size_t)(r + 0) * OUT_CH + c] = v; outp[(size_t)(r + 0) * OUT_CH + c] = v;
    v = a1 * d1; g_hs[(size_t)(r + 1) * OUT_CH + c] = v; outp[(size_t)(r + 1) * OUT_CH + c] = v;
    v = a2 * d2; g_hs[(size_t)(r + 2) * OUT_CH + c] = v; outp[(size_t)(r + 2) * OUT_CH + c] = v;
    v = a3 * d3; g_hs[(size_t)(r + 3) * OUT_CH + c] = v; outp[(size_t)(r + 3) * OUT_CH + c] = v;
}

// ---------------- final: out = dinv * out + b2 -------------------------------
__global__ void final_kernel(float* __restrict__ outp, const float* __restrict__ b2) {
    int i = blockIdx.x * blockDim.x + threadIdx.x;
    if (i < N_NODES * OUT_CH) {
        int r = i >> 6;
        int c = i & 63;
        outp[i] = fmaf(g_dinv[r], outp[i], b2[c]);
    }
}

extern "C" void kernel_launch(void* const* d_in, const int* in_sizes, int n_in,
                              void* d_out, int out_size)
{
    // ---- identify inputs by element count (robust to any metadata order) ----
    const float* x  = nullptr;
    const void*  ei = nullptr;
    const float* W1 = nullptr;
    const float* b1 = nullptr;
    const float* W2 = nullptr;
    const float* b2 = nullptr;
    for (int i = 0; i < n_in; i++) {
        long long s = in_sizes[i];
        if      (s == (long long)N_NODES * IN_CH) x  = (const float*)d_in[i];
        else if (s == 2LL * N_EDGES)              ei = d_in[i];
        else if (s == (long long)IN_CH * HID_CH)  W1 = (const float*)d_in[i];
        else if (s == (long long)HID_CH * OUT_CH) W2 = (const float*)d_in[i];
        else if (s == HID_CH) { if (!b1) b1 = (const float*)d_in[i];
                                else     b2 = (const float*)d_in[i]; }
    }
    if (!x || !ei || !W1 || !b1 || !W2 || !b2) {
        x  = (const float*)d_in[0];
        ei = d_in[1];
        W1 = (const float*)d_in[2];
        b1 = (const float*)d_in[3];
        W2 = (const float*)d_in[4];
        b2 = (const float*)d_in[5];
    }
    float* outp = (float*)d_out;

    // edge-index dtype probe + conversion to int
    probe_kernel<<<1, 256>>>(ei);
    convert_kernel<<<(N_EDGES + 255) / 256, 256>>>(ei);

    // degree + dinv
    init_deg_kernel<<<(N_NODES + 255) / 256, 256>>>();
    count_deg_kernel<<<(N_EDGES + 255) / 256, 256>>>();
    dinv_kernel<<<(N_NODES + 255) / 256, 256>>>();

    const int AGG_BLOCKS = (N_EDGES * 16) / 256;   // 100000 exactly

    // layer 1
    gemm1_kernel<<<N_NODES / 16, 256>>>(x, W1);
    agg1_kernel<<<AGG_BLOCKS, 256>>>();

    // layer 2 (epilogue1 + gemm2 fused); initializes d_out with self-loop term
    layer2_kernel<<<N_NODES / 16, 256>>>(b1, W2, outp);
    agg2_kernel<<<AGG_BLOCKS, 256>>>(outp);

    // epilogue 2
    final_kernel<<<(N_NODES * OUT_CH + 255) / 256, 256>>>(outp, b2);
}

// round 7
// speedup vs baseline: 1.4382x; 1.4323x over previous
#include <cuda_runtime.h>
#include <cuda_bf16.h>

#define N_NODES 100000
#define N_EDGES 1600000
#define IN_CH 128
#define HID_CH 64
#define OUT_CH 64

#define SCAN_CHUNK 1024
#define SCAN_BLOCKS ((N_NODES + SCAN_CHUNK - 1) / SCAN_CHUNK)   // 98

// ---------------- scratch (device globals; device-code access ONLY) ---------
__device__ int   g_idx64;
__device__ int   g_row[N_EDGES];
__device__ int   g_col[N_EDGES];
__device__ int   g_csr[N_EDGES];            // source indices grouped by dst
__device__ int   g_deg[N_NODES];            // 1 + in-degree (self-loop incl.)
__device__ int   g_start[N_NODES + 1];      // CSR offsets (edges only)
__device__ int   g_cur[N_NODES];            // scatter cursors
__device__ int   g_bsum[SCAN_BLOCKS];       // per-block scan sums
__device__ float g_dinv[N_NODES];
__device__ float g_hs [N_NODES * HID_CH];   // dinv-scaled features (msg source)
__device__ float g_acc[N_NODES * HID_CH];   // layer-1 aggregation result

// ---------------- edge-index dtype probe + convert ---------------------------
__global__ void probe_kernel(const void* ei) {
    __shared__ int ok;
    if (threadIdx.x == 0) ok = 1;
    __syncthreads();
    const long long* p = (const long long*)ei;
    for (int i = threadIdx.x; i < 1024; i += blockDim.x) {
        long long v = p[i];
        if (v < 0 || v >= N_NODES) ok = 0;
    }
    __syncthreads();
    if (threadIdx.x == 0) g_idx64 = ok;
}

__global__ void convert_kernel(const void* ei) {
    int e = blockIdx.x * blockDim.x + threadIdx.x;
    if (e >= N_EDGES) return;
    long long r, c;
    if (g_idx64) {
        const long long* p = (const long long*)ei;
        r = p[e]; c = p[e + N_EDGES];
    } else {
        const int* p = (const int*)ei;
        r = p[e]; c = p[e + N_EDGES];
    }
    if (r < 0) r = 0; if (r >= N_NODES) r = N_NODES - 1;
    if (c < 0) c = 0; if (c >= N_NODES) c = N_NODES - 1;
    g_row[e] = (int)r;
    g_col[e] = (int)c;
}

// ---------------- degree + dinv ----------------------------------------------
__global__ void init_deg_kernel() {
    int i = blockIdx.x * blockDim.x + threadIdx.x;
    if (i < N_NODES) g_deg[i] = 1;   // self-loop
}

__global__ void count_deg_kernel() {
    int e = blockIdx.x * blockDim.x + threadIdx.x;
    if (e < N_EDGES) atomicAdd(&g_deg[g_col[e]], 1);
}

__global__ void dinv_kernel() {
    int i = blockIdx.x * blockDim.x + threadIdx.x;
    if (i < N_NODES) g_dinv[i] = rsqrtf((float)g_deg[i]);
}

// ---------------- CSR build: 3-kernel exclusive scan + scatter ---------------
// scan1: per-block exclusive scan of edge counts (g_deg - 1), 1024 elems/block
__global__ void __launch_bounds__(256) scan1_kernel() {
    __shared__ int warp_sums[8];
    int b   = blockIdx.x;
    int tid = threadIdx.x;
    int base = b * SCAN_CHUNK + tid * 4;

    int v0 = 0, v1 = 0, v2 = 0, v3 = 0;
    if (base + 0 < N_NODES) v0 = g_deg[base + 0] - 1;
    if (base + 1 < N_NODES) v1 = g_deg[base + 1] - 1;
    if (base + 2 < N_NODES) v2 = g_deg[base + 2] - 1;
    if (base + 3 < N_NODES) v3 = g_deg[base + 3] - 1;
    int tsum = v0 + v1 + v2 + v3;

    int lane = tid & 31, wid = tid >> 5;
    int s = tsum;
    #pragma unroll
    for (int off = 1; off < 32; off <<= 1) {
        int t = __shfl_up_sync(0xffffffffu, s, off);
        if (lane >= off) s += t;
    }
    if (lane == 31) warp_sums[wid] = s;
    __syncthreads();
    if (tid == 0) {
        int acc = 0;
        #pragma unroll
        for (int j = 0; j < 8; j++) { int t = warp_sums[j]; warp_sums[j] = acc; acc += t; }
        g_bsum[b] = acc;
    }
    __syncthreads();

    int excl = warp_sums[wid] + (s - tsum);   // exclusive offset of this thread
    if (base + 0 < N_NODES) g_start[base + 0] = excl; excl += v0;
    if (base + 1 < N_NODES) g_start[base + 1] = excl; excl += v1;
    if (base + 2 < N_NODES) g_start[base + 2] = excl; excl += v2;
    if (base + 3 < N_NODES) g_start[base + 3] = excl;
}

// scan2: exclusive scan of the 98 block sums (serial; trivial size)
__global__ void scan2_kernel() {
    if (threadIdx.x == 0 && blockIdx.x == 0) {
        int acc = 0;
        for (int j = 0; j < SCAN_BLOCKS; j++) { int t = g_bsum[j]; g_bsum[j] = acc; acc += t; }
    }
}

// scan3: add block bases; init cursors; cap sentinel
__global__ void scan3_kernel() {
    int i = blockIdx.x * blockDim.x + threadIdx.x;
    if (i < N_NODES) {
        int v = g_start[i] + g_bsum[i / SCAN_CHUNK];
        g_start[i] = v;
        g_cur[i]   = v;
    }
    if (i == 0) g_start[N_NODES] = N_EDGES;
}

__global__ void scatter_kernel() {
    int e = blockIdx.x * blockDim.x + threadIdx.x;
    if (e >= N_EDGES) return;
    int c = g_col[e];
    int pos = atomicAdd(&g_cur[c], 1);
    g_csr[pos] = g_row[e];
}

// ---------------- layer-1 GEMM: hs = dinv * (x @ W1) -------------------------
__global__ void __launch_bounds__(256) gemm1_kernel(
    const float* __restrict__ x, const float* __restrict__ W1)
{
    __shared__ float Ws[IN_CH * HID_CH];     // 32 KB
    __shared__ float xs[16][IN_CH];          // 8 KB
    int tid = threadIdx.x;

    {
        const float4* w4 = (const float4*)W1;
        float4* ws4 = (float4*)Ws;
        #pragma unroll
        for (int i = tid; i < (IN_CH * HID_CH) / 4; i += 256) ws4[i] = w4[i];
    }
    int row0 = blockIdx.x * 16;
    {
        const float4* x4 = (const float4*)(x + (size_t)row0 * IN_CH);
        float4* xs4 = (float4*)&xs[0][0];
        #pragma unroll
        for (int i = tid; i < (16 * IN_CH) / 4; i += 256) xs4[i] = x4[i];
    }
    __syncthreads();

    int c  = tid & 63;
    int rg = tid >> 6;
    const float* x0 = xs[rg * 4 + 0];
    const float* x1 = xs[rg * 4 + 1];
    const float* x2 = xs[rg * 4 + 2];
    const float* x3 = xs[rg * 4 + 3];

    float a0 = 0.f, a1 = 0.f, a2 = 0.f, a3 = 0.f;
    #pragma unroll 8
    for (int k = 0; k < IN_CH; k++) {
        float wv = Ws[k * HID_CH + c];
        a0 = fmaf(x0[k], wv, a0);
        a1 = fmaf(x1[k], wv, a1);
        a2 = fmaf(x2[k], wv, a2);
        a3 = fmaf(x3[k], wv, a3);
    }
    int r = row0 + rg * 4;
    g_hs[(size_t)(r + 0) * HID_CH + c] = a0 * g_dinv[r + 0];
    g_hs[(size_t)(r + 1) * HID_CH + c] = a1 * g_dinv[r + 1];
    g_hs[(size_t)(r + 2) * HID_CH + c] = a2 * g_dinv[r + 2];
    g_hs[(size_t)(r + 3) * HID_CH + c] = a3 * g_dinv[r + 3];
}

// ---------------- gather-side aggregation (atomic-free) ----------------------
// 16 threads per node; each owns one float4 lane of the 64-ch feature.
__global__ void __launch_bounds__(256) agg1_kernel()
{
    int t = blockIdx.x * blockDim.x + threadIdx.x;
    int n = t >> 4;
    int q = t & 15;
    if (n >= N_NODES) return;
    const float4* s4 = (const float4*)g_hs;

    float4 a = s4[(size_t)n * 16 + q];       // self-loop term
    float sx = a.x, sy = a.y, sz = a.z, sw = a.w;

    int i   = g_start[n];
    int end = g_start[n + 1];
    for (; i + 1 < end; i += 2) {
        int r0 = g_csr[i];
        int r1 = g_csr[i + 1];
        float4 v0 = s4[(size_t)r0 * 16 + q];
        float4 v1 = s4[(size_t)r1 * 16 + q];
        sx += v0.x; sy += v0.y; sz += v0.z; sw += v0.w;
        sx += v1.x; sy += v1.y; sz += v1.z; sw += v1.w;
    }
    if (i < end) {
        int r0 = g_csr[i];
        float4 v0 = s4[(size_t)r0 * 16 + q];
        sx += v0.x; sy += v0.y; sz += v0.z; sw += v0.w;
    }
    ((float4*)g_acc)[(size_t)n * 16 + q] = make_float4(sx, sy, sz, sw);
}

// layer-2 aggregation fused with final epilogue: out = dinv[n]*sum + b2
__global__ void __launch_bounds__(256) agg2_kernel(
    float* __restrict__ outp, const float* __restrict__ b2)
{
    int t = blockIdx.x * blockDim.x + threadIdx.x;
    int n = t >> 4;
    int q = t & 15;
    if (n >= N_NODES) return;
    const float4* s4 = (const float4*)g_hs;

    float4 a = s4[(size_t)n * 16 + q];
    float sx = a.x, sy = a.y, sz = a.z, sw = a.w;

    int i   = g_start[n];
    int end = g_start[n + 1];
    for (; i + 1 < end; i += 2) {
        int r0 = g_csr[i];
        int r1 = g_csr[i + 1];
        float4 v0 = s4[(size_t)r0 * 16 + q];
        float4 v1 = s4[(size_t)r1 * 16 + q];
        sx += v0.x; sy += v0.y; sz += v0.z; sw += v0.w;
        sx += v1.x; sy += v1.y; sz += v1.z; sw += v1.w;
    }
    if (i < end) {
        int r0 = g_csr[i];
        float4 v0 = s4[(size_t)r0 * 16 + q];
        sx += v0.x; sy += v0.y; sz += v0.z; sw += v0.w;
    }
    float dv = g_dinv[n];
    float4 bb = ((const float4*)b2)[q];
    float4 o;
    o.x = fmaf(dv, sx, bb.x);
    o.y = fmaf(dv, sy, bb.y);
    o.z = fmaf(dv, sz, bb.z);
    o.w = fmaf(dv, sw, bb.w);
    ((float4*)outp)[(size_t)n * 16 + q] = o;
}

// ---------------- layer-2 GEMM: hs = dinv * (relu(dinv*acc + b1) @ W2) ------
__global__ void __launch_bounds__(256) layer2_kernel(
    const float* __restrict__ b1, const float* __restrict__ W2)
{
    __shared__ float Ws[HID_CH * OUT_CH];    // 16 KB
    __shared__ float hs[16][HID_CH];         // 4 KB
    int tid = threadIdx.x;

    {
        const float4* w4 = (const float4*)W2;
        float4* ws4 = (float4*)Ws;
        #pragma unroll
        for (int i = tid; i < (HID_CH * OUT_CH) / 4; i += 256) ws4[i] = w4[i];
    }
    int row0 = blockIdx.x * 16;
    #pragma unroll
    for (int i = tid; i < 16 * HID_CH; i += 256) {
        int rr = i >> 6;
        int cc = i & 63;
        int r  = row0 + rr;
        float v = fmaf(g_dinv[r], g_acc[(size_t)r * HID_CH + cc], __ldg(&b1[cc]));
        hs[rr][cc] = fmaxf(v, 0.f);
    }
    __syncthreads();

    int c  = tid & 63;
    int rg = tid >> 6;
    const float* x0 = hs[rg * 4 + 0];
    const float* x1 = hs[rg * 4 + 1];
    const float* x2 = hs[rg * 4 + 2];
    const float* x3 = hs[rg * 4 + 3];

    float a0 = 0.f, a1 = 0.f, a2 = 0.f, a3 = 0.f;
    #pragma unroll 8
    for (int k = 0; k < HID_CH; k++) {
        float wv = Ws[k * OUT_CH + c];
        a0 = fmaf(x0[k], wv, a0);
        a1 = fmaf(x1[k], wv, a1);
        a2 = fmaf(x2[k], wv, a2);
        a3 = fmaf(x3[k], wv, a3);
    }
    int r = row0 + rg * 4;
    g_hs[(size_t)(r + 0) * OUT_CH + c] = a0 * g_dinv[r + 0];
    g_hs[(size_t)(r + 1) * OUT_CH + c] = a1 * g_dinv[r + 1];
    g_hs[(size_t)(r + 2) * OUT_CH + c] = a2 * g_dinv[r + 2];
    g_hs[(size_t)(r + 3) * OUT_CH + c] = a3 * g_dinv[r + 3];
}

extern "C" void kernel_launch(void* const* d_in, const int* in_sizes, int n_in,
                              void* d_out, int out_size)
{
    // ---- identify inputs by element count (robust to any metadata order) ----
    const float* x  = nullptr;
    const void*  ei = nullptr;
    const float* W1 = nullptr;
    const float* b1 = nullptr;
    const float* W2 = nullptr;
    const float* b2 = nullptr;
    for (int i = 0; i < n_in; i++) {
        long long s = in_sizes[i];
        if      (s == (long long)N_NODES * IN_CH) x  = (const float*)d_in[i];
        else if (s == 2LL * N_EDGES)              ei = d_in[i];
        else if (s == (long long)IN_CH * HID_CH)  W1 = (const float*)d_in[i];
        else if (s == (long long)HID_CH * OUT_CH) W2 = (const float*)d_in[i];
        else if (s == HID_CH) { if (!b1) b1 = (const float*)d_in[i];
                                else     b2 = (const float*)d_in[i]; }
    }
    if (!x || !ei || !W1 || !b1 || !W2 || !b2) {
        x  = (const float*)d_in[0];
        ei = d_in[1];
        W1 = (const float*)d_in[2];
        b1 = (const float*)d_in[3];
        W2 = (const float*)d_in[4];
        b2 = (const float*)d_in[5];
    }
    float* outp = (float*)d_out;

    // edge-index dtype probe + conversion
    probe_kernel<<<1, 256>>>(ei);
    convert_kernel<<<(N_EDGES + 255) / 256, 256>>>(ei);

    // degree + dinv
    init_deg_kernel<<<(N_NODES + 255) / 256, 256>>>();
    count_deg_kernel<<<(N_EDGES + 255) / 256, 256>>>();
    dinv_kernel<<<(N_NODES + 255) / 256, 256>>>();

    // CSR build
    scan1_kernel<<<SCAN_BLOCKS, 256>>>();
    scan2_kernel<<<1, 32>>>();
    scan3_kernel<<<(N_NODES + 255) / 256, 256>>>();
    scatter_kernel<<<(N_EDGES + 255) / 256, 256>>>();

    const int AGG_BLOCKS = (N_NODES * 16) / 256;   // 6250 exactly

    // layer 1
    gemm1_kernel<<<N_NODES / 16, 256>>>(x, W1);
    agg1_kernel<<<AGG_BLOCKS, 256>>>();

    // layer 2
    layer2_kernel<<<N_NODES / 16, 256>>>(b1, W2);
    agg2_kernel<<<AGG_BLOCKS, 256>>>(outp, b2);
}